// round 3
// baseline (speedup 1.0000x reference)
#include <cuda_runtime.h>
#include <math.h>

#define N_PTS 8192
#define KMASK 0xFFFFE000u
#define IDXMASK 8191u

#define TPT 16                         // targets per thread
#define BT 256                         // threads per block
#define TGT_TILE (TPT*BT)              // 4096
#define TGT_CHUNKS (N_PTS/TGT_TILE)    // 2
#define SRC_TILE 32
#define SRC_CHUNKS (N_PTS/SRC_TILE)    // 256
#define TILES (TGT_CHUNKS*SRC_CHUNKS)  // 512
#define PBLOCKS 296                    // 148 SMs * occ 2
#define FB 32                          // epilogue blocks

__device__ float4 g_src4[N_PTS];       // transformed source, w = -0.5*||s||^2
__device__ float4 g_tgt4[N_PTS];       // target, w = -0.5*||t||^2
__device__ float4 g_srcn[N_PTS];       // rotated source normal, w = norm
__device__ unsigned g_rowmin[N_PTS];
__device__ unsigned g_colmin[N_PTS];
__device__ float g_part[FB][4];
__device__ int g_ticket;
__device__ unsigned g_done;

// ---- packed f32x2 helpers (Blackwell FFMA2/FADD2) -------------------------
__device__ __forceinline__ unsigned long long pk2(float lo, float hi) {
    unsigned long long d;
    asm("mov.b64 %0,{%1,%2};" : "=l"(d) : "f"(lo), "f"(hi));
    return d;
}
__device__ __forceinline__ unsigned long long add2(unsigned long long a, unsigned long long b) {
    unsigned long long d;
    asm("add.rn.f32x2 %0,%1,%2;" : "=l"(d) : "l"(a), "l"(b));
    return d;
}
__device__ __forceinline__ unsigned long long fma2(unsigned long long a, unsigned long long b, unsigned long long c) {
    unsigned long long d;
    asm("fma.rn.f32x2 %0,%1,%2,%3;" : "=l"(d) : "l"(a), "l"(b), "l"(c));
    return d;
}
__device__ __forceinline__ void upk(unsigned long long d, unsigned& lo, unsigned& hi) {
    asm("mov.b64 {%0,%1},%2;" : "=r"(lo), "=r"(hi) : "l"(d));
}

// ---------------------------------------------------------------------------
// Kernel 1: transform sources/normals (R recomputed per-thread), target
// halves, init min arrays + counters.
// ---------------------------------------------------------------------------
__global__ void k_prep(const float* __restrict__ sp, const float* __restrict__ tp,
                       const float* __restrict__ sn, const float* __restrict__ tr,
                       const float* __restrict__ sc, const float* __restrict__ r6) {
    int i = blockIdx.x * blockDim.x + threadIdx.x;
    if (i == 0) { g_ticket = 0; g_done = 0u; }
    if (i >= N_PTS) return;

    float a1x = r6[0], a1y = r6[1], a1z = r6[2];
    float a2x = r6[3], a2y = r6[4], a2z = r6[5];
    float n1 = sqrtf(a1x*a1x + a1y*a1y + a1z*a1z);
    float b1x = a1x/n1, b1y = a1y/n1, b1z = a1z/n1;
    float dd = b1x*a2x + b1y*a2y + b1z*a2z;
    float c2x = a2x - dd*b1x, c2y = a2y - dd*b1y, c2z = a2z - dd*b1z;
    float n2 = sqrtf(c2x*c2x + c2y*c2y + c2z*c2z);
    float b2x = c2x/n2, b2y = c2y/n2, b2z = c2z/n2;
    float b3x = b1y*b2z - b1z*b2y;
    float b3y = b1z*b2x - b1x*b2z;
    float b3z = b1x*b2y - b1y*b2x;
    float R0 = b1x, R1 = b2x, R2 = b3x;
    float R3 = b1y, R4 = b2y, R5 = b3y;
    float R6 = b1z, R7 = b2z, R8 = b3z;

    float t0 = tr[0], t1 = tr[1], t2 = tr[2];
    float s0 = sc[0], s1 = sc[1], s2 = sc[2];

    float px = sp[3*i+0] * s0, py = sp[3*i+1] * s1, pz = sp[3*i+2] * s2;
    float vx = R0*px + R1*py + R2*pz + t0;
    float vy = R3*px + R4*py + R5*pz + t1;
    float vz = R6*px + R7*py + R8*pz + t2;
    float hs = -0.5f * (vx*vx + vy*vy + vz*vz);
    g_src4[i] = make_float4(vx, vy, vz, hs);

    float nx = sn[3*i+0], ny = sn[3*i+1], nz = sn[3*i+2];
    float wx = R0*nx + R1*ny + R2*nz;
    float wy = R3*nx + R4*ny + R5*nz;
    float wz = R6*nx + R7*ny + R8*nz;
    float wn = sqrtf(wx*wx + wy*wy + wz*wz);
    g_srcn[i] = make_float4(wx, wy, wz, wn);

    float tx = tp[3*i+0], ty = tp[3*i+1], tz = tp[3*i+2];
    float ht = -0.5f * (tx*tx + ty*ty + tz*tz);
    g_tgt4[i] = make_float4(tx, ty, tz, ht);

    g_rowmin[i] = 0xFFFFFFFFu;
    g_colmin[i] = 0xFFFFFFFFu;
}

// ---------------------------------------------------------------------------
// Kernel 2: persistent fused pair pass. m = hs+ht+dot = -d2/2 <= 0.
// rowmin: float-max over packed keys (FMNMX, fma pipe).
// colmin: uint-min over packed keys (IMNMX, alu pipe).
// Both orderings agree with uint atomicMin for negative-float keys.
// ---------------------------------------------------------------------------
__global__ void __launch_bounds__(BT, 2) k_pairs() {
    const int tid = threadIdx.x;
    __shared__ unsigned long long sS[4][SRC_TILE];  // splatted x,y,z,w
    __shared__ int s_t;

    unsigned long long Tx[TPT/2], Ty[TPT/2], Tz[TPT/2], Tw[TPT/2];
    unsigned ck[TPT];
    unsigned cu[TPT];
    int prev_tch = -1;
    const float RINIT = __uint_as_float(0xFF7FFFFFu);  // -FLT_MAX

    for (;;) {
        if (tid == 0) s_t = atomicAdd(&g_ticket, 1);
        __syncthreads();
        const int t = s_t;
        __syncthreads();
        if (t >= TILES) break;
        const int tch = t >> 8;          // 0..1
        const int sch = t & 255;         // 0..255

        if (tch != prev_tch) {
            if (prev_tch >= 0) {
#pragma unroll
                for (int u = 0; u < TPT; u++) atomicMin(&g_colmin[cu[u]], ck[u]);
            }
            const int tbase = tch * TGT_TILE + tid;
#pragma unroll
            for (int p = 0; p < TPT/2; p++) {
                float4 a = g_tgt4[tbase + (2*p)   * BT];
                float4 b = g_tgt4[tbase + (2*p+1) * BT];
                Tx[p] = pk2(a.x, b.x);
                Ty[p] = pk2(a.y, b.y);
                Tz[p] = pk2(a.z, b.z);
                Tw[p] = pk2(a.w, b.w);
            }
#pragma unroll
            for (int u = 0; u < TPT; u++) {
                cu[u] = (unsigned)(tbase + u * BT);
                ck[u] = 0xFFFFFFFFu;
            }
            prev_tch = tch;
        }

        if (tid < SRC_TILE) {
            float4 S = g_src4[sch * SRC_TILE + tid];
            sS[0][tid] = pk2(S.x, S.x);
            sS[1][tid] = pk2(S.y, S.y);
            sS[2][tid] = pk2(S.z, S.z);
            sS[3][tid] = pk2(S.w, S.w);
        }
        __syncthreads();

        const unsigned sbase = (unsigned)(sch * SRC_TILE);
        for (int s = 0; s < SRC_TILE; s++) {
            unsigned long long Sx = sS[0][s], Sy = sS[1][s];
            unsigned long long Sz = sS[2][s], Sw = sS[3][s];
            const unsigned skey = sbase + (unsigned)s;
            float rA = RINIT, rB = RINIT;
#pragma unroll
            for (int p = 0; p < TPT/2; p++) {
                unsigned long long acc = add2(Tw[p], Sw);
                acc = fma2(Tx[p], Sx, acc);
                acc = fma2(Ty[p], Sy, acc);
                acc = fma2(Tz[p], Sz, acc);
                unsigned b0, b1;
                upk(acc, b0, b1);
                rA = fmaxf(rA, __uint_as_float((b0 & KMASK) | cu[2*p]));
                rB = fmaxf(rB, __uint_as_float((b1 & KMASK) | cu[2*p+1]));
                ck[2*p]   = umin(ck[2*p],   (b0 & KMASK) | skey);
                ck[2*p+1] = umin(ck[2*p+1], (b1 & KMASK) | skey);
            }
            float r = fmaxf(rA, rB);
#pragma unroll
            for (int off = 16; off; off >>= 1)
                r = fmaxf(r, __shfl_xor_sync(0xFFFFFFFFu, r, off));
            if ((tid & 31) == 0) atomicMin(&g_rowmin[skey], __float_as_uint(r));
        }
        __syncthreads();   // before next iteration rewrites sS / s_t
    }

    if (prev_tch >= 0) {
#pragma unroll
        for (int u = 0; u < TPT; u++) atomicMin(&g_colmin[cu[u]], ck[u]);
    }
}

// ---------------------------------------------------------------------------
// Kernel 3: exact epilogue + fused finish (last-block pattern).
// ---------------------------------------------------------------------------
__global__ void k_final(const float* __restrict__ tn, float* __restrict__ out) {
    const int tid = threadIdx.x;
    const int i = blockIdx.x * BT + tid;
    const float EPS = 1e-6f;

    float v0, v1, v2, v3;
    {
        int j = (int)(g_rowmin[i] & IDXMASK);
        float4 S = g_src4[i];
        float4 T = g_tgt4[j];
        float ns  = S.x*S.x + S.y*S.y + S.z*S.z;
        float nt2 = T.x*T.x + T.y*T.y + T.z*T.z;
        float dp  = S.x*T.x + S.y*T.y + S.z*T.z;
        v0 = fmaxf(ns + nt2 - 2.f*dp, 0.f);

        float4 Nn = g_srcn[i];
        float ax = tn[3*j+0], ay = tn[3*j+1], az = tn[3*j+2];
        float an = sqrtf(ax*ax + ay*ay + az*az);
        float cs = (Nn.x*ax + Nn.y*ay + Nn.z*az) /
                   (fmaxf(Nn.w, EPS) * fmaxf(an, EPS));
        v2 = 1.f - fabsf(cs);
    }
    {
        int j = (int)(g_colmin[i] & IDXMASK);
        float4 T = g_tgt4[i];
        float4 S = g_src4[j];
        float ns  = S.x*S.x + S.y*S.y + S.z*S.z;
        float nt2 = T.x*T.x + T.y*T.y + T.z*T.z;
        float dp  = S.x*T.x + S.y*T.y + S.z*T.z;
        v1 = fmaxf(ns + nt2 - 2.f*dp, 0.f);

        float ax = tn[3*i+0], ay = tn[3*i+1], az = tn[3*i+2];
        float an = sqrtf(ax*ax + ay*ay + az*az);
        float4 Sn = g_srcn[j];
        float cs = (ax*Sn.x + ay*Sn.y + az*Sn.z) /
                   (fmaxf(an, EPS) * fmaxf(Sn.w, EPS));
        v3 = 1.f - fabsf(cs);
    }

    // deterministic block reduction
    float v[4] = {v0, v1, v2, v3};
#pragma unroll
    for (int k = 0; k < 4; k++)
#pragma unroll
        for (int off = 16; off; off >>= 1)
            v[k] += __shfl_xor_sync(0xFFFFFFFFu, v[k], off);

    __shared__ float sh[8][4];
    __shared__ bool s_last;
    const int warp = tid >> 5;
    if ((tid & 31) == 0) {
        sh[warp][0] = v[0]; sh[warp][1] = v[1];
        sh[warp][2] = v[2]; sh[warp][3] = v[3];
    }
    __syncthreads();
    if (tid == 0) {
#pragma unroll
        for (int k = 0; k < 4; k++) {
            float p = 0.f;
#pragma unroll
            for (int w = 0; w < 8; w++) p += sh[w][k];
            g_part[blockIdx.x][k] = p;
        }
        __threadfence();
        s_last = (atomicAdd(&g_done, 1u) == (unsigned)(FB - 1));
    }
    __syncthreads();

    if (s_last && tid < 32) {
        __threadfence();
        float w[4];
#pragma unroll
        for (int k = 0; k < 4; k++) w[k] = g_part[tid][k];
#pragma unroll
        for (int k = 0; k < 4; k++)
#pragma unroll
            for (int off = 16; off; off >>= 1)
                w[k] += __shfl_xor_sync(0xFFFFFFFFu, w[k], off);
        if (tid == 0) {
            const float invN = 1.0f / (float)N_PTS;
            out[0] = w[0]*invN + w[1]*invN + 0.1f*(w[2]*invN + w[3]*invN);
        }
    }
}

// ---------------------------------------------------------------------------
extern "C" void kernel_launch(void* const* d_in, const int* in_sizes, int n_in,
                              void* d_out, int out_size) {
    const float* sp = (const float*)d_in[0];
    const float* tp = (const float*)d_in[1];
    const float* sn = (const float*)d_in[2];
    const float* tn = (const float*)d_in[3];
    const float* tr = (const float*)d_in[4];
    const float* r6 = (const float*)d_in[5];
    const float* sc = (const float*)d_in[6];
    float* out = (float*)d_out;

    k_prep<<<N_PTS / BT, BT>>>(sp, tp, sn, tr, sc, r6);
    k_pairs<<<PBLOCKS, BT>>>();
    k_final<<<FB, BT>>>(tn, out);
}

// round 4
// speedup vs baseline: 1.2281x; 1.2281x over previous
#include <cuda_runtime.h>
#include <math.h>

#define N_PTS 8192
#define KMASK 0xFFFFE000u
#define IDXMASK 8191u

#define TPT 16                        // targets per thread (register resident)
#define BT 256                        // threads per block
#define TGT_TILE (TPT*BT)             // 4096
#define TGT_CHUNKS (N_PTS/TGT_TILE)   // 2
#define SRC_TILE 64
#define SRC_CHUNKS (N_PTS/SRC_TILE)   // 128  -> grid 256 blocks = 1 wave @ occ2
#define FB 32                         // epilogue blocks

__device__ float4 g_src4[N_PTS];      // transformed source, w = -0.5*||s||^2
__device__ float4 g_tgt4[N_PTS];      // target, w = -0.5*||t||^2
__device__ float4 g_srcn[N_PTS];      // rotated source normal, w = norm
__device__ unsigned g_rowmin[N_PTS];
__device__ unsigned g_colmin[N_PTS];
__device__ float g_part[FB][4];
__device__ unsigned g_done;

// ---- packed f32x2 helpers (Blackwell FFMA2/FADD2) -------------------------
__device__ __forceinline__ unsigned long long pk2(float lo, float hi) {
    unsigned long long d;
    asm("mov.b64 %0,{%1,%2};" : "=l"(d) : "f"(lo), "f"(hi));
    return d;
}
__device__ __forceinline__ unsigned long long add2(unsigned long long a, unsigned long long b) {
    unsigned long long d;
    asm("add.rn.f32x2 %0,%1,%2;" : "=l"(d) : "l"(a), "l"(b));
    return d;
}
__device__ __forceinline__ unsigned long long fma2(unsigned long long a, unsigned long long b, unsigned long long c) {
    unsigned long long d;
    asm("fma.rn.f32x2 %0,%1,%2,%3;" : "=l"(d) : "l"(a), "l"(b), "l"(c));
    return d;
}
__device__ __forceinline__ void upk(unsigned long long d, unsigned& lo, unsigned& hi) {
    asm("mov.b64 {%0,%1},%2;" : "=r"(lo), "=r"(hi) : "l"(d));
}

// ---------------------------------------------------------------------------
// Kernel 1: transform sources/normals (R recomputed per-thread, trivial),
// target halves, init min arrays + done counter.
// ---------------------------------------------------------------------------
__global__ void k_prep(const float* __restrict__ sp, const float* __restrict__ tp,
                       const float* __restrict__ sn, const float* __restrict__ tr,
                       const float* __restrict__ sc, const float* __restrict__ r6) {
    int i = blockIdx.x * blockDim.x + threadIdx.x;
    if (i == 0) g_done = 0u;
    if (i >= N_PTS) return;

    float a1x = r6[0], a1y = r6[1], a1z = r6[2];
    float a2x = r6[3], a2y = r6[4], a2z = r6[5];
    float n1 = sqrtf(a1x*a1x + a1y*a1y + a1z*a1z);
    float b1x = a1x/n1, b1y = a1y/n1, b1z = a1z/n1;
    float dd = b1x*a2x + b1y*a2y + b1z*a2z;
    float c2x = a2x - dd*b1x, c2y = a2y - dd*b1y, c2z = a2z - dd*b1z;
    float n2 = sqrtf(c2x*c2x + c2y*c2y + c2z*c2z);
    float b2x = c2x/n2, b2y = c2y/n2, b2z = c2z/n2;
    float b3x = b1y*b2z - b1z*b2y;
    float b3y = b1z*b2x - b1x*b2z;
    float b3z = b1x*b2y - b1y*b2x;
    float R0 = b1x, R1 = b2x, R2 = b3x;
    float R3 = b1y, R4 = b2y, R5 = b3y;
    float R6 = b1z, R7 = b2z, R8 = b3z;

    float t0 = tr[0], t1 = tr[1], t2 = tr[2];
    float s0 = sc[0], s1 = sc[1], s2 = sc[2];

    float px = sp[3*i+0] * s0, py = sp[3*i+1] * s1, pz = sp[3*i+2] * s2;
    float vx = R0*px + R1*py + R2*pz + t0;
    float vy = R3*px + R4*py + R5*pz + t1;
    float vz = R6*px + R7*py + R8*pz + t2;
    float hs = -0.5f * (vx*vx + vy*vy + vz*vz);
    g_src4[i] = make_float4(vx, vy, vz, hs);

    float nx = sn[3*i+0], ny = sn[3*i+1], nz = sn[3*i+2];
    float wx = R0*nx + R1*ny + R2*nz;
    float wy = R3*nx + R4*ny + R5*nz;
    float wz = R6*nx + R7*ny + R8*nz;
    float wn = sqrtf(wx*wx + wy*wy + wz*wz);
    g_srcn[i] = make_float4(wx, wy, wz, wn);

    float tx = tp[3*i+0], ty = tp[3*i+1], tz = tp[3*i+2];
    float ht = -0.5f * (tx*tx + ty*ty + tz*tz);
    g_tgt4[i] = make_float4(tx, ty, tz, ht);

    g_rowmin[i] = 0xFFFFFFFFu;
    g_colmin[i] = 0xFFFFFFFFu;
}

// ---------------------------------------------------------------------------
// Kernel 2: fused pair pass, f32x2-packed, static grid (2 x 128).
// m = hs + ht + dot(s,t) = -d2/2 <= 0.
// rowmin accumulates as float-max (FMNMX, fma pipe); colmin as uint-min
// (IMNMX, alu pipe). For negative-float keys both agree with uint atomicMin.
// ---------------------------------------------------------------------------
__global__ void __launch_bounds__(BT, 2) k_pairs() {
    const int tchunk = blockIdx.x;          // 0..1
    const int schunk = blockIdx.y;          // 0..127
    const int tid = threadIdx.x;

    __shared__ unsigned long long sS[4][SRC_TILE];  // splatted x,y,z,w

    unsigned long long Tx[TPT/2], Ty[TPT/2], Tz[TPT/2], Tw[TPT/2];
    unsigned ck[TPT];
    unsigned cu[TPT];
    const int tbase = tchunk * TGT_TILE + tid;
#pragma unroll
    for (int p = 0; p < TPT/2; p++) {
        float4 a = g_tgt4[tbase + (2*p)   * BT];
        float4 b = g_tgt4[tbase + (2*p+1) * BT];
        Tx[p] = pk2(a.x, b.x);
        Ty[p] = pk2(a.y, b.y);
        Tz[p] = pk2(a.z, b.z);
        Tw[p] = pk2(a.w, b.w);
    }
#pragma unroll
    for (int u = 0; u < TPT; u++) {
        ck[u] = 0xFFFFFFFFu;
        cu[u] = (unsigned)(tbase + u * BT);
    }

    const int sbase = schunk * SRC_TILE;
    {
        // 256 threads, 64 sources: thread t<64 loads source t
        if (tid < SRC_TILE) {
            float4 S = g_src4[sbase + tid];
            sS[0][tid] = pk2(S.x, S.x);
            sS[1][tid] = pk2(S.y, S.y);
            sS[2][tid] = pk2(S.z, S.z);
            sS[3][tid] = pk2(S.w, S.w);
        }
    }
    __syncthreads();

    const float RINIT = __uint_as_float(0xFF7FFFFFu);  // -FLT_MAX
    for (int s = 0; s < SRC_TILE; s++) {
        unsigned long long Sx = sS[0][s], Sy = sS[1][s];
        unsigned long long Sz = sS[2][s], Sw = sS[3][s];
        const unsigned skey = (unsigned)(sbase + s);
        float rA = RINIT, rB = RINIT;
#pragma unroll
        for (int p = 0; p < TPT/2; p++) {
            unsigned long long acc = add2(Tw[p], Sw);
            acc = fma2(Tx[p], Sx, acc);
            acc = fma2(Ty[p], Sy, acc);
            acc = fma2(Tz[p], Sz, acc);
            unsigned b0, b1;
            upk(acc, b0, b1);
            rA = fmaxf(rA, __uint_as_float((b0 & KMASK) | cu[2*p]));
            rB = fmaxf(rB, __uint_as_float((b1 & KMASK) | cu[2*p+1]));
            ck[2*p]   = umin(ck[2*p],   (b0 & KMASK) | skey);
            ck[2*p+1] = umin(ck[2*p+1], (b1 & KMASK) | skey);
        }
        float r = fmaxf(rA, rB);
#pragma unroll
        for (int off = 16; off; off >>= 1)
            r = fmaxf(r, __shfl_xor_sync(0xFFFFFFFFu, r, off));
        if ((tid & 31) == 0) atomicMin(&g_rowmin[skey], __float_as_uint(r));
    }

#pragma unroll
    for (int u = 0; u < TPT; u++)
        atomicMin(&g_colmin[cu[u]], ck[u]);
}

// ---------------------------------------------------------------------------
// Kernel 3: exact epilogue + fused finish (last-block-done pattern).
// ---------------------------------------------------------------------------
__global__ void k_final(const float* __restrict__ tn, float* __restrict__ out) {
    const int tid = threadIdx.x;
    const int i = blockIdx.x * BT + tid;
    const float EPS = 1e-6f;

    float v0, v1, v2, v3;
    {
        int j = (int)(g_rowmin[i] & IDXMASK);
        float4 S = g_src4[i];
        float4 T = g_tgt4[j];
        float ns  = S.x*S.x + S.y*S.y + S.z*S.z;
        float nt2 = T.x*T.x + T.y*T.y + T.z*T.z;
        float dp  = S.x*T.x + S.y*T.y + S.z*T.z;
        v0 = fmaxf(ns + nt2 - 2.f*dp, 0.f);

        float4 Nn = g_srcn[i];
        float ax = tn[3*j+0], ay = tn[3*j+1], az = tn[3*j+2];
        float an = sqrtf(ax*ax + ay*ay + az*az);
        float cs = (Nn.x*ax + Nn.y*ay + Nn.z*az) /
                   (fmaxf(Nn.w, EPS) * fmaxf(an, EPS));
        v2 = 1.f - fabsf(cs);
    }
    {
        int j = (int)(g_colmin[i] & IDXMASK);
        float4 T = g_tgt4[i];
        float4 S = g_src4[j];
        float ns  = S.x*S.x + S.y*S.y + S.z*S.z;
        float nt2 = T.x*T.x + T.y*T.y + T.z*T.z;
        float dp  = S.x*T.x + S.y*T.y + S.z*T.z;
        v1 = fmaxf(ns + nt2 - 2.f*dp, 0.f);

        float ax = tn[3*i+0], ay = tn[3*i+1], az = tn[3*i+2];
        float an = sqrtf(ax*ax + ay*ay + az*az);
        float4 Sn = g_srcn[j];
        float cs = (ax*Sn.x + ay*Sn.y + az*Sn.z) /
                   (fmaxf(an, EPS) * fmaxf(Sn.w, EPS));
        v3 = 1.f - fabsf(cs);
    }

    // deterministic block reduction
    float v[4] = {v0, v1, v2, v3};
#pragma unroll
    for (int k = 0; k < 4; k++)
#pragma unroll
        for (int off = 16; off; off >>= 1)
            v[k] += __shfl_xor_sync(0xFFFFFFFFu, v[k], off);

    __shared__ float sh[8][4];
    __shared__ bool s_last;
    const int warp = tid >> 5;
    if ((tid & 31) == 0) {
        sh[warp][0] = v[0]; sh[warp][1] = v[1];
        sh[warp][2] = v[2]; sh[warp][3] = v[3];
    }
    __syncthreads();
    if (tid == 0) {
#pragma unroll
        for (int k = 0; k < 4; k++) {
            float p = 0.f;
#pragma unroll
            for (int w = 0; w < 8; w++) p += sh[w][k];
            g_part[blockIdx.x][k] = p;
        }
        __threadfence();
        s_last = (atomicAdd(&g_done, 1u) == (unsigned)(FB - 1));
    }
    __syncthreads();

    if (s_last && tid < 32) {
        __threadfence();
        float w[4];
#pragma unroll
        for (int k = 0; k < 4; k++) w[k] = g_part[tid][k];
#pragma unroll
        for (int k = 0; k < 4; k++)
#pragma unroll
            for (int off = 16; off; off >>= 1)
                w[k] += __shfl_xor_sync(0xFFFFFFFFu, w[k], off);
        if (tid == 0) {
            const float invN = 1.0f / (float)N_PTS;
            out[0] = w[0]*invN + w[1]*invN + 0.1f*(w[2]*invN + w[3]*invN);
        }
    }
}

// ---------------------------------------------------------------------------
extern "C" void kernel_launch(void* const* d_in, const int* in_sizes, int n_in,
                              void* d_out, int out_size) {
    const float* sp = (const float*)d_in[0];
    const float* tp = (const float*)d_in[1];
    const float* sn = (const float*)d_in[2];
    const float* tn = (const float*)d_in[3];
    const float* tr = (const float*)d_in[4];
    const float* r6 = (const float*)d_in[5];
    const float* sc = (const float*)d_in[6];
    float* out = (float*)d_out;

    k_prep<<<64, 128>>>(sp, tp, sn, tr, sc, r6);
    dim3 grid(TGT_CHUNKS, SRC_CHUNKS);
    k_pairs<<<grid, BT>>>();
    k_final<<<FB, BT>>>(tn, out);
}

// round 5
// speedup vs baseline: 1.2883x; 1.0491x over previous
#include <cuda_runtime.h>
#include <math.h>

#define N_PTS 8192
#define KMASK 0xFFFFE000u
#define IDXMASK 8191u

#define TPT 16                        // targets per thread (register resident)
#define BT 256                        // threads per block
#define TGT_TILE (TPT*BT)             // 4096
#define TGT_CHUNKS (N_PTS/TGT_TILE)   // 2
#define SRC_TILE 64
#define SRC_CHUNKS (N_PTS/SRC_TILE)   // 128  -> grid 256 blocks = 1 wave @ occ2
#define FB 32                         // epilogue blocks

__device__ unsigned g_rowmin[N_PTS];
__device__ unsigned g_colmin[N_PTS];
__device__ float g_part[FB][4];
__device__ unsigned g_done;           // static-init 0; finisher resets to 0

// ---- packed f32x2 helpers (Blackwell FFMA2/FADD2) -------------------------
__device__ __forceinline__ unsigned long long pk2(float lo, float hi) {
    unsigned long long d;
    asm("mov.b64 %0,{%1,%2};" : "=l"(d) : "f"(lo), "f"(hi));
    return d;
}
__device__ __forceinline__ unsigned long long add2(unsigned long long a, unsigned long long b) {
    unsigned long long d;
    asm("add.rn.f32x2 %0,%1,%2;" : "=l"(d) : "l"(a), "l"(b));
    return d;
}
__device__ __forceinline__ unsigned long long fma2(unsigned long long a, unsigned long long b, unsigned long long c) {
    unsigned long long d;
    asm("fma.rn.f32x2 %0,%1,%2,%3;" : "=l"(d) : "l"(a), "l"(b), "l"(c));
    return d;
}
__device__ __forceinline__ void upk(unsigned long long d, unsigned& lo, unsigned& hi) {
    asm("mov.b64 {%0,%1},%2;" : "=r"(lo), "=r"(hi) : "l"(d));
}

// rotation_6d -> R (row-major), ~30 instr, recomputed per thread where needed
__device__ __forceinline__ void make_R(const float* __restrict__ r6, float R[9]) {
    float a1x = r6[0], a1y = r6[1], a1z = r6[2];
    float a2x = r6[3], a2y = r6[4], a2z = r6[5];
    float n1 = sqrtf(a1x*a1x + a1y*a1y + a1z*a1z);
    float b1x = a1x/n1, b1y = a1y/n1, b1z = a1z/n1;
    float dd = b1x*a2x + b1y*a2y + b1z*a2z;
    float c2x = a2x - dd*b1x, c2y = a2y - dd*b1y, c2z = a2z - dd*b1z;
    float n2 = sqrtf(c2x*c2x + c2y*c2y + c2z*c2z);
    float b2x = c2x/n2, b2y = c2y/n2, b2z = c2z/n2;
    R[0] = b1x; R[1] = b2x; R[2] = b1y*b2z - b1z*b2y;
    R[3] = b1y; R[4] = b2y; R[5] = b1z*b2x - b1x*b2z;
    R[6] = b1z; R[7] = b2z; R[8] = b1x*b2y - b1y*b2x;
}

// ---------------------------------------------------------------------------
// Kernel 1: self-contained fused pair pass, f32x2-packed, static grid (2x128).
// m = -0.5*||s||^2 - 0.5*||t||^2 + dot(s,t) = -d2/2 <= 0.
// For negative floats: smaller d2 <=> larger m <=> smaller uint(bits).
// key = (bits(m) & KMASK) | idx -> umin = fused min+argmin.
// ---------------------------------------------------------------------------
__global__ void __launch_bounds__(BT, 2) k_pairs(const float* __restrict__ sp,
                                                 const float* __restrict__ tp,
                                                 const float* __restrict__ tr,
                                                 const float* __restrict__ r6,
                                                 const float* __restrict__ sc) {
    const int tchunk = blockIdx.x;          // 0..1
    const int schunk = blockIdx.y;          // 0..127
    const int tid = threadIdx.x;

    __shared__ unsigned long long sS[4][SRC_TILE];  // splatted x,y,z,w

    // --- source tile: transform 64 raw sources (threads < SRC_TILE) ---
    const int sbase = schunk * SRC_TILE;
    if (tid < SRC_TILE) {
        float R[9];
        make_R(r6, R);
        float t0 = tr[0], t1 = tr[1], t2 = tr[2];
        float s0 = sc[0], s1 = sc[1], s2 = sc[2];
        int i = sbase + tid;
        float px = sp[3*i+0] * s0, py = sp[3*i+1] * s1, pz = sp[3*i+2] * s2;
        float vx = R[0]*px + R[1]*py + R[2]*pz + t0;
        float vy = R[3]*px + R[4]*py + R[5]*pz + t1;
        float vz = R[6]*px + R[7]*py + R[8]*pz + t2;
        float hs = -0.5f * (vx*vx + vy*vy + vz*vz);
        sS[0][tid] = pk2(vx, vx);
        sS[1][tid] = pk2(vy, vy);
        sS[2][tid] = pk2(vz, vz);
        sS[3][tid] = pk2(hs, hs);
    }

    // --- target tile: 16 raw targets per thread, ht inline ---
    unsigned long long Tx[TPT/2], Ty[TPT/2], Tz[TPT/2], Tw[TPT/2];
    unsigned ck[TPT];
    unsigned cu[TPT];
    const int tbase = tchunk * TGT_TILE + tid;
#pragma unroll
    for (int p = 0; p < TPT/2; p++) {
        int ia = tbase + (2*p)   * BT;
        int ib = tbase + (2*p+1) * BT;
        float ax = tp[3*ia+0], ay = tp[3*ia+1], az = tp[3*ia+2];
        float bx = tp[3*ib+0], by = tp[3*ib+1], bz = tp[3*ib+2];
        float ha = -0.5f*(ax*ax + ay*ay + az*az);
        float hb = -0.5f*(bx*bx + by*by + bz*bz);
        Tx[p] = pk2(ax, bx);
        Ty[p] = pk2(ay, by);
        Tz[p] = pk2(az, bz);
        Tw[p] = pk2(ha, hb);
    }
#pragma unroll
    for (int u = 0; u < TPT; u++) {
        ck[u] = 0xFFFFFFFFu;
        cu[u] = (unsigned)(tbase + u * BT);
    }
    __syncthreads();

    for (int s = 0; s < SRC_TILE; s++) {
        unsigned long long Sx = sS[0][s], Sy = sS[1][s];
        unsigned long long Sz = sS[2][s], Sw = sS[3][s];
        const unsigned skey = (unsigned)(sbase + s);
        unsigned rloc = 0xFFFFFFFFu;
#pragma unroll
        for (int p = 0; p < TPT/2; p++) {
            unsigned long long acc = add2(Tw[p], Sw);
            acc = fma2(Tx[p], Sx, acc);
            acc = fma2(Ty[p], Sy, acc);
            acc = fma2(Tz[p], Sz, acc);
            unsigned b0, b1;
            upk(acc, b0, b1);
            rloc      = umin(rloc,      (b0 & KMASK) | cu[2*p]);
            rloc      = umin(rloc,      (b1 & KMASK) | cu[2*p+1]);
            ck[2*p]   = umin(ck[2*p],   (b0 & KMASK) | skey);
            ck[2*p+1] = umin(ck[2*p+1], (b1 & KMASK) | skey);
        }
        // one-instruction warp reduce (REDUX.SYNC.MIN.U32)
        rloc = __reduce_min_sync(0xFFFFFFFFu, rloc);
        if ((tid & 31) == 0) atomicMin(&g_rowmin[skey], rloc);
    }

#pragma unroll
    for (int u = 0; u < TPT; u++)
        atomicMin(&g_colmin[cu[u]], ck[u]);
}

// ---------------------------------------------------------------------------
// Kernel 2: self-contained exact epilogue + fused finish.
// Recomputes transforms from raw inputs for point i and its partners.
// ---------------------------------------------------------------------------
__global__ void k_final(const float* __restrict__ sp, const float* __restrict__ tp,
                        const float* __restrict__ sn, const float* __restrict__ tn,
                        const float* __restrict__ tr, const float* __restrict__ r6,
                        const float* __restrict__ sc, float* __restrict__ out) {
    const int tid = threadIdx.x;
    const int i = blockIdx.x * BT + tid;
    const float EPS = 1e-6f;

    float R[9];
    make_R(r6, R);
    const float t0 = tr[0], t1 = tr[1], t2 = tr[2];
    const float s0 = sc[0], s1 = sc[1], s2 = sc[2];

    // transform source i
    float six, siy, siz, nix, niy, niz, nin;
    {
        float px = sp[3*i+0]*s0, py = sp[3*i+1]*s1, pz = sp[3*i+2]*s2;
        six = R[0]*px + R[1]*py + R[2]*pz + t0;
        siy = R[3]*px + R[4]*py + R[5]*pz + t1;
        siz = R[6]*px + R[7]*py + R[8]*pz + t2;
        float nx = sn[3*i+0], ny = sn[3*i+1], nz = sn[3*i+2];
        nix = R[0]*nx + R[1]*ny + R[2]*nz;
        niy = R[3]*nx + R[4]*ny + R[5]*nz;
        niz = R[6]*nx + R[7]*ny + R[8]*nz;
        nin = sqrtf(nix*nix + niy*niy + niz*niz);
    }
    float tix = tp[3*i+0], tiy = tp[3*i+1], tiz = tp[3*i+2];

    float v0, v1, v2, v3;
    {
        // source i -> target j
        int j = (int)(g_rowmin[i] & IDXMASK);
        float tx = tp[3*j+0], ty = tp[3*j+1], tz = tp[3*j+2];
        float ns  = six*six + siy*siy + siz*siz;
        float nt2 = tx*tx + ty*ty + tz*tz;
        float dp  = six*tx + siy*ty + siz*tz;
        v0 = fmaxf(ns + nt2 - 2.f*dp, 0.f);

        float ax = tn[3*j+0], ay = tn[3*j+1], az = tn[3*j+2];
        float an = sqrtf(ax*ax + ay*ay + az*az);
        float cs = (nix*ax + niy*ay + niz*az) /
                   (fmaxf(nin, EPS) * fmaxf(an, EPS));
        v2 = 1.f - fabsf(cs);
    }
    {
        // target i -> source j (transform source j)
        int j = (int)(g_colmin[i] & IDXMASK);
        float px = sp[3*j+0]*s0, py = sp[3*j+1]*s1, pz = sp[3*j+2]*s2;
        float sx = R[0]*px + R[1]*py + R[2]*pz + t0;
        float sy = R[3]*px + R[4]*py + R[5]*pz + t1;
        float sz = R[6]*px + R[7]*py + R[8]*pz + t2;
        float ns  = sx*sx + sy*sy + sz*sz;
        float nt2 = tix*tix + tiy*tiy + tiz*tiz;
        float dp  = sx*tix + sy*tiy + sz*tiz;
        v1 = fmaxf(ns + nt2 - 2.f*dp, 0.f);

        float ax = tn[3*i+0], ay = tn[3*i+1], az = tn[3*i+2];
        float an = sqrtf(ax*ax + ay*ay + az*az);
        float nx = sn[3*j+0], ny = sn[3*j+1], nz = sn[3*j+2];
        float wx = R[0]*nx + R[1]*ny + R[2]*nz;
        float wy = R[3]*nx + R[4]*ny + R[5]*nz;
        float wz = R[6]*nx + R[7]*ny + R[8]*nz;
        float wn = sqrtf(wx*wx + wy*wy + wz*wz);
        float cs = (ax*wx + ay*wy + az*wz) /
                   (fmaxf(an, EPS) * fmaxf(wn, EPS));
        v3 = 1.f - fabsf(cs);
    }

    // deterministic block reduction
    float v[4] = {v0, v1, v2, v3};
#pragma unroll
    for (int k = 0; k < 4; k++)
#pragma unroll
        for (int off = 16; off; off >>= 1)
            v[k] += __shfl_xor_sync(0xFFFFFFFFu, v[k], off);

    __shared__ float sh[8][4];
    __shared__ bool s_last;
    const int warp = tid >> 5;
    if ((tid & 31) == 0) {
        sh[warp][0] = v[0]; sh[warp][1] = v[1];
        sh[warp][2] = v[2]; sh[warp][3] = v[3];
    }
    __syncthreads();
    if (tid == 0) {
#pragma unroll
        for (int k = 0; k < 4; k++) {
            float p = 0.f;
#pragma unroll
            for (int w = 0; w < 8; w++) p += sh[w][k];
            g_part[blockIdx.x][k] = p;
        }
        __threadfence();
        s_last = (atomicAdd(&g_done, 1u) == (unsigned)(FB - 1));
    }
    __syncthreads();

    if (s_last && tid < 32) {
        __threadfence();
        float w[4];
#pragma unroll
        for (int k = 0; k < 4; k++) w[k] = g_part[tid][k];
#pragma unroll
        for (int k = 0; k < 4; k++)
#pragma unroll
            for (int off = 16; off; off >>= 1)
                w[k] += __shfl_xor_sync(0xFFFFFFFFu, w[k], off);
        if (tid == 0) {
            const float invN = 1.0f / (float)N_PTS;
            out[0] = w[0]*invN + w[1]*invN + 0.1f*(w[2]*invN + w[3]*invN);
            g_done = 0u;   // reset for next replay (deterministic)
        }
    }
}

// ---------------------------------------------------------------------------
extern "C" void kernel_launch(void* const* d_in, const int* in_sizes, int n_in,
                              void* d_out, int out_size) {
    const float* sp = (const float*)d_in[0];
    const float* tp = (const float*)d_in[1];
    const float* sn = (const float*)d_in[2];
    const float* tn = (const float*)d_in[3];
    const float* tr = (const float*)d_in[4];
    const float* r6 = (const float*)d_in[5];
    const float* sc = (const float*)d_in[6];
    float* out = (float*)d_out;

    void *rm = nullptr, *cm = nullptr;
    cudaGetSymbolAddress(&rm, g_rowmin);
    cudaGetSymbolAddress(&cm, g_colmin);
    cudaMemsetAsync(rm, 0xFF, N_PTS * sizeof(unsigned), 0);
    cudaMemsetAsync(cm, 0xFF, N_PTS * sizeof(unsigned), 0);

    dim3 grid(TGT_CHUNKS, SRC_CHUNKS);
    k_pairs<<<grid, BT>>>(sp, tp, tr, r6, sc);
    k_final<<<FB, BT>>>(sp, tp, sn, tn, tr, r6, sc, out);
}

// round 6
// speedup vs baseline: 1.3647x; 1.0593x over previous
#include <cuda_runtime.h>
#include <math.h>

#define N_PTS 8192
#define KMASK 0xFFFFE000u
#define IDXMASK 8191u

#define TPT 16                        // targets per thread (register resident)
#define BT 256                        // threads per block (pair pass)
#define TGT_TILE (TPT*BT)             // 4096
#define TGT_CHUNKS (N_PTS/TGT_TILE)   // 2
#define SRC_TILE 64
#define SRC_CHUNKS (N_PTS/SRC_TILE)   // 128  -> grid 256 blocks = 1 wave @ occ2
#define FB 64                         // epilogue blocks
#define FT 128                        // epilogue threads/block

// Stored value = ~packed_key, accumulated with atomicMax.
// packed_key = (bits(m) & KMASK) | idx, m = -d2/2 (finite) => key <= 0xFF7FFFFF
// => ~key >= 0x00800000 > 0, so zero-init always loses. Static device globals
// are zero-initialized; k_final resets entries to 0 after reading (replay-safe).
__device__ unsigned g_rowmin[N_PTS];
__device__ unsigned g_colmin[N_PTS];
__device__ float g_part[FB][4];
__device__ unsigned g_done;           // static-init 0; finisher resets to 0

// ---- packed f32x2 helpers (Blackwell FFMA2/FADD2) -------------------------
__device__ __forceinline__ unsigned long long pk2(float lo, float hi) {
    unsigned long long d;
    asm("mov.b64 %0,{%1,%2};" : "=l"(d) : "f"(lo), "f"(hi));
    return d;
}
__device__ __forceinline__ unsigned long long add2(unsigned long long a, unsigned long long b) {
    unsigned long long d;
    asm("add.rn.f32x2 %0,%1,%2;" : "=l"(d) : "l"(a), "l"(b));
    return d;
}
__device__ __forceinline__ unsigned long long fma2(unsigned long long a, unsigned long long b, unsigned long long c) {
    unsigned long long d;
    asm("fma.rn.f32x2 %0,%1,%2,%3;" : "=l"(d) : "l"(a), "l"(b), "l"(c));
    return d;
}
__device__ __forceinline__ void upk(unsigned long long d, unsigned& lo, unsigned& hi) {
    asm("mov.b64 {%0,%1},%2;" : "=r"(lo), "=r"(hi) : "l"(d));
}

// rotation_6d -> R (row-major)
__device__ __forceinline__ void make_R(const float* __restrict__ r6, float R[9]) {
    float a1x = r6[0], a1y = r6[1], a1z = r6[2];
    float a2x = r6[3], a2y = r6[4], a2z = r6[5];
    float n1 = sqrtf(a1x*a1x + a1y*a1y + a1z*a1z);
    float b1x = a1x/n1, b1y = a1y/n1, b1z = a1z/n1;
    float dd = b1x*a2x + b1y*a2y + b1z*a2z;
    float c2x = a2x - dd*b1x, c2y = a2y - dd*b1y, c2z = a2z - dd*b1z;
    float n2 = sqrtf(c2x*c2x + c2y*c2y + c2z*c2z);
    float b2x = c2x/n2, b2y = c2y/n2, b2z = c2z/n2;
    R[0] = b1x; R[1] = b2x; R[2] = b1y*b2z - b1z*b2y;
    R[3] = b1y; R[4] = b2y; R[5] = b1z*b2x - b1x*b2z;
    R[6] = b1z; R[7] = b2z; R[8] = b1x*b2y - b1y*b2x;
}

// ---------------------------------------------------------------------------
// Kernel 1: self-contained fused pair pass, f32x2-packed, static grid (2x128).
// ---------------------------------------------------------------------------
__global__ void __launch_bounds__(BT, 2) k_pairs(const float* __restrict__ sp,
                                                 const float* __restrict__ tp,
                                                 const float* __restrict__ tr,
                                                 const float* __restrict__ r6,
                                                 const float* __restrict__ sc) {
    const int tchunk = blockIdx.x;          // 0..1
    const int schunk = blockIdx.y;          // 0..127
    const int tid = threadIdx.x;

    __shared__ ulonglong2 sS[SRC_TILE][2];  // [s][0]={x,y} [s][1]={z,w} splatted

    // --- source tile: transform 64 raw sources (threads < SRC_TILE) ---
    const int sbase = schunk * SRC_TILE;
    if (tid < SRC_TILE) {
        float R[9];
        make_R(r6, R);
        float t0 = tr[0], t1 = tr[1], t2 = tr[2];
        float s0 = sc[0], s1 = sc[1], s2 = sc[2];
        int i = sbase + tid;
        float px = sp[3*i+0] * s0, py = sp[3*i+1] * s1, pz = sp[3*i+2] * s2;
        float vx = R[0]*px + R[1]*py + R[2]*pz + t0;
        float vy = R[3]*px + R[4]*py + R[5]*pz + t1;
        float vz = R[6]*px + R[7]*py + R[8]*pz + t2;
        float hs = -0.5f * (vx*vx + vy*vy + vz*vz);
        sS[tid][0] = make_ulonglong2(pk2(vx, vx), pk2(vy, vy));
        sS[tid][1] = make_ulonglong2(pk2(vz, vz), pk2(hs, hs));
    }

    // --- target tile: 16 raw targets per thread, ht inline ---
    unsigned long long Tx[TPT/2], Ty[TPT/2], Tz[TPT/2], Tw[TPT/2];
    unsigned ck[TPT];
    unsigned cu[TPT];
    const int tbase = tchunk * TGT_TILE + tid;
#pragma unroll
    for (int p = 0; p < TPT/2; p++) {
        int ia = tbase + (2*p)   * BT;
        int ib = tbase + (2*p+1) * BT;
        float ax = tp[3*ia+0], ay = tp[3*ia+1], az = tp[3*ia+2];
        float bx = tp[3*ib+0], by = tp[3*ib+1], bz = tp[3*ib+2];
        float ha = -0.5f*(ax*ax + ay*ay + az*az);
        float hb = -0.5f*(bx*bx + by*by + bz*bz);
        Tx[p] = pk2(ax, bx);
        Ty[p] = pk2(ay, by);
        Tz[p] = pk2(az, bz);
        Tw[p] = pk2(ha, hb);
    }
#pragma unroll
    for (int u = 0; u < TPT; u++) {
        ck[u] = 0xFFFFFFFFu;
        cu[u] = (unsigned)(tbase + u * BT);
    }
    __syncthreads();

    for (int s = 0; s < SRC_TILE; s++) {
        ulonglong2 a = sS[s][0];
        ulonglong2 b2v = sS[s][1];
        unsigned long long Sx = a.x, Sy = a.y, Sz = b2v.x, Sw = b2v.y;
        const unsigned skey = (unsigned)(sbase + s);
        unsigned rloc = 0xFFFFFFFFu;
#pragma unroll
        for (int p = 0; p < TPT/2; p++) {
            unsigned long long acc = add2(Tw[p], Sw);
            acc = fma2(Tx[p], Sx, acc);
            acc = fma2(Ty[p], Sy, acc);
            acc = fma2(Tz[p], Sz, acc);
            unsigned b0, b1;
            upk(acc, b0, b1);
            rloc      = umin(rloc,      (b0 & KMASK) | cu[2*p]);
            rloc      = umin(rloc,      (b1 & KMASK) | cu[2*p+1]);
            ck[2*p]   = umin(ck[2*p],   (b0 & KMASK) | skey);
            ck[2*p+1] = umin(ck[2*p+1], (b1 & KMASK) | skey);
        }
        rloc = __reduce_min_sync(0xFFFFFFFFu, rloc);   // REDUX.SYNC.MIN
        if ((tid & 31) == 0) atomicMax(&g_rowmin[skey], ~rloc);
    }

#pragma unroll
    for (int u = 0; u < TPT; u++)
        atomicMax(&g_colmin[cu[u]], ~ck[u]);
}

// ---------------------------------------------------------------------------
// Kernel 2: self-contained exact epilogue + fused finish + state reset.
// ---------------------------------------------------------------------------
__global__ void k_final(const float* __restrict__ sp, const float* __restrict__ tp,
                        const float* __restrict__ sn, const float* __restrict__ tn,
                        const float* __restrict__ tr, const float* __restrict__ r6,
                        const float* __restrict__ sc, float* __restrict__ out) {
    const int tid = threadIdx.x;
    const int i = blockIdx.x * FT + tid;
    const float EPS = 1e-6f;

    // read winners, reset entries to 0 for next replay (single reader each)
    unsigned rv = g_rowmin[i];
    unsigned cv = g_colmin[i];
    g_rowmin[i] = 0u;
    g_colmin[i] = 0u;
    int jr = (int)((~rv) & IDXMASK);
    int jc = (int)((~cv) & IDXMASK);

    float R[9];
    make_R(r6, R);
    const float t0 = tr[0], t1 = tr[1], t2 = tr[2];
    const float s0 = sc[0], s1 = sc[1], s2 = sc[2];

    // transform source i and its normal
    float six, siy, siz, nix, niy, niz, nin;
    {
        float px = sp[3*i+0]*s0, py = sp[3*i+1]*s1, pz = sp[3*i+2]*s2;
        six = R[0]*px + R[1]*py + R[2]*pz + t0;
        siy = R[3]*px + R[4]*py + R[5]*pz + t1;
        siz = R[6]*px + R[7]*py + R[8]*pz + t2;
        float nx = sn[3*i+0], ny = sn[3*i+1], nz = sn[3*i+2];
        nix = R[0]*nx + R[1]*ny + R[2]*nz;
        niy = R[3]*nx + R[4]*ny + R[5]*nz;
        niz = R[6]*nx + R[7]*ny + R[8]*nz;
        nin = sqrtf(nix*nix + niy*niy + niz*niz);
    }
    float tix = tp[3*i+0], tiy = tp[3*i+1], tiz = tp[3*i+2];

    float v0, v1, v2, v3;
    {
        // source i -> target jr
        float tx = tp[3*jr+0], ty = tp[3*jr+1], tz = tp[3*jr+2];
        float ns  = six*six + siy*siy + siz*siz;
        float nt2 = tx*tx + ty*ty + tz*tz;
        float dp  = six*tx + siy*ty + siz*tz;
        v0 = fmaxf(ns + nt2 - 2.f*dp, 0.f);

        float ax = tn[3*jr+0], ay = tn[3*jr+1], az = tn[3*jr+2];
        float an = sqrtf(ax*ax + ay*ay + az*az);
        float cs = (nix*ax + niy*ay + niz*az) /
                   (fmaxf(nin, EPS) * fmaxf(an, EPS));
        v2 = 1.f - fabsf(cs);
    }
    {
        // target i -> source jc (transform source jc)
        float px = sp[3*jc+0]*s0, py = sp[3*jc+1]*s1, pz = sp[3*jc+2]*s2;
        float sx = R[0]*px + R[1]*py + R[2]*pz + t0;
        float sy = R[3]*px + R[4]*py + R[5]*pz + t1;
        float sz = R[6]*px + R[7]*py + R[8]*pz + t2;
        float ns  = sx*sx + sy*sy + sz*sz;
        float nt2 = tix*tix + tiy*tiy + tiz*tiz;
        float dp  = sx*tix + sy*tiy + sz*tiz;
        v1 = fmaxf(ns + nt2 - 2.f*dp, 0.f);

        float ax = tn[3*i+0], ay = tn[3*i+1], az = tn[3*i+2];
        float an = sqrtf(ax*ax + ay*ay + az*az);
        float nx = sn[3*jc+0], ny = sn[3*jc+1], nz = sn[3*jc+2];
        float wx = R[0]*nx + R[1]*ny + R[2]*nz;
        float wy = R[3]*nx + R[4]*ny + R[5]*nz;
        float wz = R[6]*nx + R[7]*ny + R[8]*nz;
        float wn = sqrtf(wx*wx + wy*wy + wz*wz);
        float cs = (ax*wx + ay*wy + az*wz) /
                   (fmaxf(an, EPS) * fmaxf(wn, EPS));
        v3 = 1.f - fabsf(cs);
    }

    // deterministic block reduction (4 warps)
    float v[4] = {v0, v1, v2, v3};
#pragma unroll
    for (int k = 0; k < 4; k++)
#pragma unroll
        for (int off = 16; off; off >>= 1)
            v[k] += __shfl_xor_sync(0xFFFFFFFFu, v[k], off);

    __shared__ float sh[4][4];
    __shared__ bool s_last;
    const int warp = tid >> 5;
    if ((tid & 31) == 0) {
        sh[warp][0] = v[0]; sh[warp][1] = v[1];
        sh[warp][2] = v[2]; sh[warp][3] = v[3];
    }
    __syncthreads();
    if (tid == 0) {
#pragma unroll
        for (int k = 0; k < 4; k++) {
            float p = 0.f;
#pragma unroll
            for (int w = 0; w < 4; w++) p += sh[w][k];
            g_part[blockIdx.x][k] = p;
        }
        __threadfence();
        s_last = (atomicAdd(&g_done, 1u) == (unsigned)(FB - 1));
    }
    __syncthreads();

    if (s_last && tid < 32) {
        __threadfence();
        float w[4];
#pragma unroll
        for (int k = 0; k < 4; k++)
            w[k] = g_part[tid][k] + g_part[tid + 32][k];
#pragma unroll
        for (int k = 0; k < 4; k++)
#pragma unroll
            for (int off = 16; off; off >>= 1)
                w[k] += __shfl_xor_sync(0xFFFFFFFFu, w[k], off);
        if (tid == 0) {
            const float invN = 1.0f / (float)N_PTS;
            out[0] = w[0]*invN + w[1]*invN + 0.1f*(w[2]*invN + w[3]*invN);
            g_done = 0u;   // reset for next replay
        }
    }
}

// ---------------------------------------------------------------------------
extern "C" void kernel_launch(void* const* d_in, const int* in_sizes, int n_in,
                              void* d_out, int out_size) {
    const float* sp = (const float*)d_in[0];
    const float* tp = (const float*)d_in[1];
    const float* sn = (const float*)d_in[2];
    const float* tn = (const float*)d_in[3];
    const float* tr = (const float*)d_in[4];
    const float* r6 = (const float*)d_in[5];
    const float* sc = (const float*)d_in[6];
    float* out = (float*)d_out;

    dim3 grid(TGT_CHUNKS, SRC_CHUNKS);
    k_pairs<<<grid, BT>>>(sp, tp, tr, r6, sc);
    k_final<<<FB, FT>>>(sp, tp, sn, tn, tr, r6, sc, out);
}